// round 7
// baseline (speedup 1.0000x reference)
#include <cuda_runtime.h>
#include <math.h>

#define Bb 64
#define Nn 1024
#define Hh 64
#define Tt 10
#define DST 132   // dup-buffer row stride in words (16B-aligned rows, bank-safe)

// ---------------- scratch (device globals) ------------------------------------
__device__ __align__(16) float g_emb[Bb*Nn*Hh];
__device__ __align__(16) float g_h1 [Bb*Nn*Hh];
__device__ __align__(16) float g_h2 [Bb*Nn*Hh];
__device__ __align__(16) float g_G  [Bb*Tt*Hh*Hh];
__device__ __align__(16) float g_M  [Bb*Tt*Hh*Hh];
__device__ __align__(16) float g_inv[Bb*Nn];
__device__ int   g_idx[Bb*Tt*Nn];
__device__ int   g_cnt[Bb*Tt];
__device__ __align__(16) float g_ctx[Bb*Hh];

typedef unsigned long long ull;

#define FMA4(A, s, v) { (A).x += (s)*(v).x; (A).y += (s)*(v).y; (A).z += (s)*(v).z; (A).w += (s)*(v).w; }
#define FMA2(acc, a2, b2)  asm("fma.rn.f32x2 %0, %1, %2, %0;" : "+l"(acc) : "l"(a2), "l"(b2))
#define PACK_DUP(out, x)   asm("mov.b64 %0, {%1, %1};" : "=l"(out) : "r"(__float_as_uint(x)))
#define UNPACK2(lo, hi, p) asm("mov.b64 {%0, %1}, %2;" : "=r"(lo), "=r"(hi) : "l"(p))

__device__ __forceinline__ float4 acc_f4(ull p0, ull p1) {
    unsigned a, b, c, d;
    UNPACK2(a, b, p0); UNPACK2(c, d, p1);
    return make_float4(__uint_as_float(a), __uint_as_float(b),
                       __uint_as_float(c), __uint_as_float(d));
}

// 16 fp32 FMAs: 4 pre-duplicated a-pairs x one float4 of B. No PACK in hot loop.
__device__ __forceinline__ void mk16du(ull* acc, ull a0, ull a1, ull a2, ull a3,
                                       const float* bp) {
    ulonglong2 bv = *(const ulonglong2*)bp;
    FMA2(acc[0], a0, bv.x); FMA2(acc[1], a0, bv.y);
    FMA2(acc[2], a1, bv.x); FMA2(acc[3], a1, bv.y);
    FMA2(acc[4], a2, bv.x); FMA2(acc[5], a2, bv.y);
    FMA2(acc[6], a3, bv.x); FMA2(acc[7], a3, bv.y);
}

// store float4 v as duplicated pairs {x,x,y,y,z,z,w,w} at p (16B aligned)
__device__ __forceinline__ void st_dup(float* p, float4 v) {
    *(float4*)p       = make_float4(v.x, v.x, v.y, v.y);
    *(float4*)(p + 4) = make_float4(v.z, v.z, v.w, v.w);
}

// ---------------- K1: encoder (blocks 0..1023) + bucket (1024..1087) -----------
// dyn smem: SD dup-h1 8448 | SW2 w2t 4352  = 51200 B
__global__ __launch_bounds__(256, 4) void k_encbkt(
    const float* __restrict__ tf, const int* __restrict__ types,
    const float* __restrict__ w1, const float* __restrict__ b1,
    const float* __restrict__ w2, const float* __restrict__ b2)
{
    extern __shared__ __align__(16) float sm[];
    float* SD  = sm;           // dup h1 [row][2k] stride DST
    float* SW2 = sm + 8448;    // w2^T [k][j] stride 68
    __shared__ float s_f[192];
    __shared__ float s_w1[192];
    __shared__ float s_b1[64];
    __shared__ __align__(16) float s_b2[64];
    __shared__ int s_cnt[16];
    int tid = threadIdx.x;

    if (blockIdx.x >= 1024) {               // ---- bucket path ----
        int b = blockIdx.x - 1024;
        if (tid < Tt) s_cnt[tid] = 0;
        if (tid < 64) g_ctx[b*64 + tid] = 0.f;
        __syncthreads();
        #pragma unroll
        for (int it = 0; it < 4; ++it) {
            int n = it*256 + tid;
            int t = types[b*Nn + n];
            int pos = atomicAdd(&s_cnt[t], 1);
            g_idx[(b*Tt + t)*Nn + pos] = n;
        }
        __syncthreads();
        if (tid < Tt) g_cnt[b*Tt + tid] = s_cnt[tid];
        return;
    }

    int tx = tid & 15, ty = tid >> 4;
    int base = blockIdx.x * 64;

    #pragma unroll
    for (int it = 0; it < 16; ++it) {
        int e = tid + it*256;
        int j = e >> 6, k = e & 63;
        SW2[k*68 + j] = w2[e];
    }
    if (tid < 192) { s_f[tid] = tf[base*3 + tid]; s_w1[tid] = w1[tid]; }
    if (tid < 64)  { s_b1[tid] = b1[tid]; s_b2[tid] = b2[tid]; }
    __syncthreads();

    // h1 = relu(W1 f + b1), stored duplicated
    #pragma unroll
    for (int it = 0; it < 16; ++it) {
        int e = tid + it*256;
        int row = e >> 6, k = e & 63;
        float h = s_f[row*3+0]*s_w1[k*3+0] + s_f[row*3+1]*s_w1[k*3+1]
                + s_f[row*3+2]*s_w1[k*3+2] + s_b1[k];
        h = fmaxf(h, 0.f);
        ull hh; PACK_DUP(hh, h);
        *(ull*)&SD[row*DST + 2*k] = hh;
    }
    __syncthreads();

    const ull* A0 = (const ull*)&SD[(ty*4+0)*DST];
    const ull* A1 = (const ull*)&SD[(ty*4+1)*DST];
    const ull* A2 = (const ull*)&SD[(ty*4+2)*DST];
    const ull* A3 = (const ull*)&SD[(ty*4+3)*DST];
    ull acc[8] = {0,0,0,0,0,0,0,0};
    #pragma unroll 8
    for (int kk = 0; kk < 64; ++kk)
        mk16du(acc, A0[kk], A1[kk], A2[kk], A3[kk], &SW2[kk*68 + tx*4]);

    float4 bias = *(const float4*)&s_b2[tx*4];
    #pragma unroll
    for (int i = 0; i < 4; ++i) {
        float4 v = acc_f4(acc[2*i], acc[2*i+1]);
        v.x += bias.x; v.y += bias.y; v.z += bias.z; v.w += bias.w;
        float sq = v.x*v.x + v.y*v.y + v.z*v.z + v.w*v.w;
        #pragma unroll
        for (int o = 8; o > 0; o >>= 1) sq += __shfl_xor_sync(0xffffffffu, sq, o);
        float inv = 1.f / fmaxf(sqrtf(sq), 1e-12f);
        int r = base + ty*4 + i;
        *(float4*)&g_emb[r*64 + tx*4] = v;
        if (tx == 0) g_inv[r] = inv;
    }
}

// ---------------- K2: G_t = Nrm^T @ H per (t,b) --------------------------------
// dyn smem: SD dup-nrm 8448 | SB h 4096 = 50176 B
__global__ __launch_bounds__(256, 4) void k_gmat(int layer)
{
    const float4* emb4 = (const float4*)g_emb;
    const float4* h4   = (const float4*)((layer == 0) ? g_emb : g_h1);
    extern __shared__ __align__(16) float sm[];
    float* SD = sm;           // dup nrm [rr][2i] stride DST
    float* SB = sm + 8448;    // h [rr][j] stride 64
    int t = blockIdx.x, b = blockIdx.y;
    int tid = threadIdx.x;
    int tx = tid & 15, ty = tid >> 4;
    int Kt = g_cnt[b*Tt + t];
    const int* lst = &g_idx[(b*Tt + t)*Nn];
    ull acc[8] = {0,0,0,0,0,0,0,0};

    for (int r0 = 0; r0 < Kt; r0 += 64) {
        #pragma unroll
        for (int it = 0; it < 4; ++it) {
            int e = tid + it*256;
            int rr = e >> 4, kq = e & 15;
            int r = r0 + rr;
            float4 v = make_float4(0.f,0.f,0.f,0.f);
            float4 w = v;
            if (r < Kt) {
                int row = __ldg(&lst[r]);
                float iv = __ldg(&g_inv[(b<<10) + row]);
                int gi = ((b<<10) + row)*16 + kq;
                v = emb4[gi];
                w = (layer == 0) ? v : h4[gi];
                v.x *= iv; v.y *= iv; v.z *= iv; v.w *= iv;
            }
            *(float4*)&SB[rr*64 + kq*4] = w;
            st_dup(&SD[rr*DST + kq*8], v);
        }
        __syncthreads();
        #pragma unroll 8
        for (int rr = 0; rr < 64; ++rr) {
            ulonglong2 a01 = *(const ulonglong2*)&SD[rr*DST + ty*8];
            ulonglong2 a23 = *(const ulonglong2*)&SD[rr*DST + ty*8 + 4];
            mk16du(acc, a01.x, a01.y, a23.x, a23.y, &SB[rr*64 + tx*4]);
        }
        __syncthreads();
    }
    float* Gp = &g_G[(b*Tt + t)*4096];
    #pragma unroll
    for (int i = 0; i < 4; ++i)
        *(float4*)&Gp[(ty*4 + i)*64 + tx*4] = acc_f4(acc[2*i], acc[2*i+1]);
}

// ---------------- K2b: M[b,tp] = sum_t sigmoid(C[tp,t]) G[b,t] -----------------
__global__ __launch_bounds__(128) void k_combine(const float* __restrict__ cont)
{
    __shared__ float s_S[Tt*Tt];
    int b = blockIdx.x, tid = threadIdx.x;
    if (tid < Tt*Tt) s_S[tid] = 1.f / (1.f + expf(-cont[tid]));
    __syncthreads();
    int i4 = blockIdx.y * 128 + tid;
    const float4* G4 = (const float4*)g_G + (size_t)b*10240;
    float4*       M4 = (float4*)g_M       + (size_t)b*10240;
    float4 g[Tt];
    #pragma unroll
    for (int t = 0; t < Tt; ++t) g[t] = G4[t*1024 + i4];
    #pragma unroll
    for (int tp = 0; tp < Tt; ++tp) {
        float4 o = make_float4(0.f,0.f,0.f,0.f);
        #pragma unroll
        for (int t = 0; t < Tt; ++t) {
            float s = s_S[tp*Tt + t];
            FMA4(o, s, g[t]);
        }
        M4[tp*1024 + i4] = o;
    }
}

// ---------------- K3: Agg = Nrm @ M ; Hout = relu((H+Agg)@W^T+b) ---------------
// dyn smem: SM_M 4096 | SW 4352 | SD dup (nrm/X aliased) 8448 = 67584 B
__global__ __launch_bounds__(256, 3) void k_layer(
    int layer, const float* __restrict__ gnn_w, const float* __restrict__ gnn_b)
{
    const float* hin  = (layer == 0) ? g_emb : g_h1;
    float*       hout = (layer == 0) ? g_h1  : g_h2;
    const float4* emb4 = (const float4*)g_emb;
    extern __shared__ __align__(16) float sm[];
    float* SM_ = sm;           // M   [k][c] stride 64
    float* SW  = sm + 4096;    // W^T [k][c] stride 68
    float* SD  = sm + 8448;    // dup [r][2k] stride DST (nrm, then X)
    __shared__ __align__(16) float s_bias[64];
    __shared__ __align__(16) float s_csum[16][64];

    int t = blockIdx.x, b = blockIdx.y;
    int tid = threadIdx.x;
    int tx = tid & 15, ty = tid >> 4;
    int Kt = g_cnt[b*Tt + t];
    if (Kt == 0) return;

    const float* Wp = gnn_w + layer*4096;
    if (tid < 64) s_bias[tid] = gnn_b[layer*64 + tid];
    #pragma unroll
    for (int it = 0; it < 16; ++it) {
        int e = tid + it*256;
        SW[(e & 63)*68 + (e >> 6)] = Wp[e];     // transpose -> [k][c]
    }
    const float4* Mp4 = (const float4*)&g_M[(b*Tt + t)*4096];
    #pragma unroll
    for (int it = 0; it < 4; ++it) {
        int e = tid + it*256;
        *(float4*)&SM_[e*4] = Mp4[e];           // natural [k][c], linear copy
    }

    const int* lst = &g_idx[(b*Tt + t)*Nn];
    const ull* A0 = (const ull*)&SD[(ty*4+0)*DST];
    const ull* A1 = (const ull*)&SD[(ty*4+1)*DST];
    const ull* A2 = (const ull*)&SD[(ty*4+2)*DST];
    const ull* A3 = (const ull*)&SD[(ty*4+3)*DST];
    float4 psum = make_float4(0.f,0.f,0.f,0.f);
    __syncthreads();

    for (int r0 = 0; r0 < Kt; r0 += 64) {
        // gather scaled nrm (duplicated layout)
        #pragma unroll
        for (int it = 0; it < 4; ++it) {
            int e = tid + it*256;
            int rr = e >> 4, kq = e & 15;
            int r = r0 + rr;
            float4 v = make_float4(0.f,0.f,0.f,0.f);
            if (r < Kt) {
                int row = __ldg(&lst[r]);
                float iv = __ldg(&g_inv[(b<<10) + row]);
                v = emb4[((b<<10) + row)*16 + kq];
                v.x *= iv; v.y *= iv; v.z *= iv; v.w *= iv;
            }
            st_dup(&SD[rr*DST + kq*8], v);
        }
        __syncthreads();

        // GEMM1: Agg = nrm @ M
        ull acc[8] = {0,0,0,0,0,0,0,0};
        #pragma unroll 8
        for (int kk = 0; kk < 64; ++kk)
            mk16du(acc, A0[kk], A1[kk], A2[kk], A3[kk], &SM_[kk*64 + tx*4]);

        // X = H + Agg (held in regs across the sync)
        float4 x[4];
        #pragma unroll
        for (int i = 0; i < 4; ++i) {
            int r = r0 + ty*4 + i;
            x[i] = acc_f4(acc[2*i], acc[2*i+1]);
            if (r < Kt) {
                int row = __ldg(&lst[r]);
                float4 hv = *(const float4*)&hin[((b<<10) + row)*64 + tx*4];
                x[i].x += hv.x; x[i].y += hv.y; x[i].z += hv.z; x[i].w += hv.w;
            } else {
                x[i] = make_float4(0.f,0.f,0.f,0.f);
            }
        }
        __syncthreads();      // all GEMM1 reads of SD done
        #pragma unroll
        for (int i = 0; i < 4; ++i)
            st_dup(&SD[(ty*4+i)*DST + tx*8], x[i]);
        __syncthreads();

        // GEMM2: Out = X @ W^T
        ull acc2[8] = {0,0,0,0,0,0,0,0};
        #pragma unroll 8
        for (int kk = 0; kk < 64; ++kk)
            mk16du(acc2, A0[kk], A1[kk], A2[kk], A3[kk], &SW[kk*68 + tx*4]);

        float4 bias = *(const float4*)&s_bias[tx*4];
        #pragma unroll
        for (int i = 0; i < 4; ++i) {
            int r = r0 + ty*4 + i;
            if (r < Kt) {
                int row = __ldg(&lst[r]);
                float4 o = acc_f4(acc2[2*i], acc2[2*i+1]);
                o.x = fmaxf(o.x + bias.x, 0.f);
                o.y = fmaxf(o.y + bias.y, 0.f);
                o.z = fmaxf(o.z + bias.z, 0.f);
                o.w = fmaxf(o.w + bias.w, 0.f);
                *(float4*)&hout[((b<<10) + row)*64 + tx*4] = o;
                if (layer == 1) { psum.x += o.x; psum.y += o.y; psum.z += o.z; psum.w += o.w; }
            }
        }
        __syncthreads();      // before next gather overwrites SD
    }

    if (layer == 1) {
        *(float4*)&s_csum[ty][tx*4] = psum;
        __syncthreads();
        if (tid < 64) {
            float s = 0.f;
            #pragma unroll
            for (int q = 0; q < 16; ++q) s += s_csum[q][tid];
            atomicAdd(&g_ctx[b*64 + tid], s);
        }
    }
}

// ---------------- K4: head (+GRU computed per-block, K reduced to 64) ----------
// dyn smem: SD dup-X 8448 | SW w1t 4352 = 51200 B
__global__ __launch_bounds__(256, 4) void k_head(
    const float* __restrict__ prev, const float* __restrict__ wih,
    const float* __restrict__ whh,  const float* __restrict__ bih,
    const float* __restrict__ bhh,
    const float* __restrict__ w1, const float* __restrict__ b1,
    const float* __restrict__ w2, const float* __restrict__ b2,
    float* __restrict__ out)
{
    extern __shared__ __align__(16) float sm[];
    float* SD = sm;           // dup X [r][2k] stride DST
    float* SW = sm + 8448;    // W1[:, :64]^T [k][j] stride 68
    __shared__ __align__(16) float s_g[320];   // ctx|prev|gi|gh|ns
    __shared__ __align__(16) float s_hs[64];
    __shared__ __align__(16) float s_w2[64];
    int tid = threadIdx.x;
    int tx = tid & 15, ty = tid >> 4;
    int u = blockIdx.x;
    int base = u << 6;
    int b = u >> 4;

    if (tid < 64)  s_g[tid] = g_ctx[b*64 + tid] * (1.f/1024.f);
    else if (tid < 96) s_g[tid] = prev[b*32 + (tid - 64)];
    #pragma unroll
    for (int it = 0; it < 16; ++it) {
        int e = tid + it*256;
        int j = e >> 6, k = e & 63;
        SW[k*68 + j] = w1[j*96 + k];
    }
    if (tid < 64) s_w2[tid] = w2[tid];
    const float4* h24 = (const float4*)g_h2;
    #pragma unroll
    for (int it = 0; it < 4; ++it) {
        int e = tid + it*256;
        int rr = e >> 4, kq = e & 15;
        st_dup(&SD[rr*DST + kq*8], h24[(base + rr)*16 + kq]);
    }
    __syncthreads();

    if (tid < 96) {
        float gi = bih[tid], gh = bhh[tid];
        #pragma unroll 16
        for (int k = 0; k < 64; ++k) gi += s_g[k] * wih[tid*64 + k];
        #pragma unroll 16
        for (int k = 0; k < 32; ++k) gh += s_g[64 + k] * whh[tid*32 + k];
        s_g[96 + tid] = gi; s_g[192 + tid] = gh;
    }
    __syncthreads();
    if (tid < 32) {
        float r  = 1.f / (1.f + expf(-(s_g[96  + tid] + s_g[192 + tid])));
        float z  = 1.f / (1.f + expf(-(s_g[128 + tid] + s_g[224 + tid])));
        float nn = tanhf(s_g[160 + tid] + r * s_g[256 + tid]);
        float ns = (1.f - z)*nn + z*s_g[64 + tid];
        s_g[288 + tid] = ns;
        if ((u & 15) == 0) out[Bb*Nn + b*32 + tid] = ns;
    }
    __syncthreads();
    if (tid < 64) {
        float v = b1[tid];
        #pragma unroll
        for (int k = 0; k < 32; ++k) v += w1[tid*96 + 64 + k] * s_g[288 + k];
        s_hs[tid] = v;
    }
    __syncthreads();

    const ull* A0 = (const ull*)&SD[(ty*4+0)*DST];
    const ull* A1 = (const ull*)&SD[(ty*4+1)*DST];
    const ull* A2 = (const ull*)&SD[(ty*4+2)*DST];
    const ull* A3 = (const ull*)&SD[(ty*4+3)*DST];
    ulonglong2 h01 = *(const ulonglong2*)&s_hs[tx*4];
    ull acc[8] = {h01.x, h01.y, h01.x, h01.y, h01.x, h01.y, h01.x, h01.y};
    #pragma unroll 8
    for (int kk = 0; kk < 64; ++kk)
        mk16du(acc, A0[kk], A1[kk], A2[kk], A3[kk], &SW[kk*68 + tx*4]);

    float4 w2v = *(const float4*)&s_w2[tx*4];
    float b2v = b2[0];
    #pragma unroll
    for (int i = 0; i < 4; ++i) {
        float4 v = acc_f4(acc[2*i], acc[2*i+1]);
        float y = fmaxf(v.x, 0.f)*w2v.x + fmaxf(v.y, 0.f)*w2v.y
                + fmaxf(v.z, 0.f)*w2v.z + fmaxf(v.w, 0.f)*w2v.w;
        #pragma unroll
        for (int o = 8; o > 0; o >>= 1) y += __shfl_xor_sync(0xffffffffu, y, o);
        if (tx == 0) out[base + ty*4 + i] = y + b2v;
    }
}

// ---------------- launch --------------------------------------------------------
extern "C" void kernel_launch(void* const* d_in, const int* in_sizes, int n_in,
                              void* d_out, int out_size)
{
    const float* tf    = (const float*)d_in[0];
    const int*   types = (const int*)  d_in[1];
    const float* prev  = (const float*)d_in[2];
    const float* ew1   = (const float*)d_in[3];
    const float* eb1   = (const float*)d_in[4];
    const float* ew2   = (const float*)d_in[5];
    const float* eb2   = (const float*)d_in[6];
    const float* cont  = (const float*)d_in[7];
    const float* gw    = (const float*)d_in[8];
    const float* gb    = (const float*)d_in[9];
    const float* wih   = (const float*)d_in[10];
    const float* whh   = (const float*)d_in[11];
    const float* bih   = (const float*)d_in[12];
    const float* bhh   = (const float*)d_in[13];
    const float* hw1   = (const float*)d_in[14];
    const float* hb1   = (const float*)d_in[15];
    const float* hw2   = (const float*)d_in[16];
    const float* hb2   = (const float*)d_in[17];
    float* out = (float*)d_out;

    cudaFuncSetAttribute(k_encbkt, cudaFuncAttributeMaxDynamicSharedMemorySize, 51200);
    cudaFuncSetAttribute(k_gmat,   cudaFuncAttributeMaxDynamicSharedMemorySize, 50176);
    cudaFuncSetAttribute(k_layer,  cudaFuncAttributeMaxDynamicSharedMemorySize, 67584);
    cudaFuncSetAttribute(k_head,   cudaFuncAttributeMaxDynamicSharedMemorySize, 51200);

    k_encbkt<<<1088, 256, 51200>>>(tf, types, ew1, eb1, ew2, eb2);
    for (int l = 0; l < 2; ++l) {
        k_gmat   <<<dim3(Tt, Bb), 256, 50176>>>(l);
        k_combine<<<dim3(Bb, 8), 128>>>(cont);
        k_layer  <<<dim3(Tt, Bb), 256, 67584>>>(l, gw, gb);
    }
    k_head<<<1024, 256, 51200>>>(prev, wih, whh, bih, bhh, hw1, hb1, hw2, hb2, out);
}

// round 8
// speedup vs baseline: 1.1233x; 1.1233x over previous
#include <cuda_runtime.h>
#include <math.h>

#define Bb 64
#define Nn 1024
#define Hh 64
#define Tt 10

// ---------------- scratch (device globals) ------------------------------------
__device__ __align__(16) float g_emb[Bb*Nn*Hh];
__device__ __align__(16) float g_h1 [Bb*Nn*Hh];
__device__ __align__(16) float g_h2 [Bb*Nn*Hh];
__device__ __align__(16) float g_G  [Bb*Tt*Hh*Hh];
__device__ __align__(16) float g_M  [Bb*Tt*Hh*Hh];
__device__ __align__(16) float g_inv[Bb*Nn];
__device__ int   g_idx[Bb*Tt*Nn];
__device__ int   g_cnt[Bb*Tt];
__device__ __align__(16) float g_ctx[Bb*Hh];

#define FMA4(A, s, v) { (A).x += (s)*(v).x; (A).y += (s)*(v).y; (A).z += (s)*(v).z; (A).w += (s)*(v).w; }

// ---------------- K1: encoder (blocks 0..1023) + bucket (1024..1087) -----------
__global__ __launch_bounds__(256) void k_encbkt(
    const float* __restrict__ tf, const int* __restrict__ types,
    const float* __restrict__ w1, const float* __restrict__ b1,
    const float* __restrict__ w2, const float* __restrict__ b2)
{
    __shared__ __align__(16) float s_h1 [64*68];
    __shared__ __align__(16) float s_w2t[64*68];
    __shared__ __align__(16) float s_f[192];
    __shared__ __align__(16) float s_w1[192];
    __shared__ __align__(16) float s_b1[64];
    __shared__ __align__(16) float s_b2[64];
    __shared__ int s_cnt[16];
    int tid = threadIdx.x;

    if (blockIdx.x >= 1024) {               // ---- bucket path ----
        int b = blockIdx.x - 1024;
        if (tid < Tt) s_cnt[tid] = 0;
        if (tid < 64) g_ctx[b*64 + tid] = 0.f;
        __syncthreads();
        #pragma unroll
        for (int it = 0; it < 4; ++it) {
            int n = it*256 + tid;
            int t = types[b*Nn + n];
            int pos = atomicAdd(&s_cnt[t], 1);
            g_idx[(b*Tt + t)*Nn + pos] = n;
        }
        __syncthreads();
        if (tid < Tt) g_cnt[b*Tt + tid] = s_cnt[tid];
        return;
    }

    int tx = tid & 15, ty = tid >> 4;
    int base = blockIdx.x * 64;

    // w2 transposed: s_w2t[k][j] = w2[j*64+k]
    #pragma unroll
    for (int it = 0; it < 16; ++it) {
        int e = tid + it*256;
        int j = e >> 6, k = e & 63;
        s_w2t[k*68 + j] = w2[e];
    }
    if (tid < 192) { s_f[tid] = tf[base*3 + tid]; s_w1[tid] = w1[tid]; }
    if (tid < 64)  { s_b1[tid] = b1[tid]; s_b2[tid] = b2[tid]; }
    __syncthreads();

    // h1 = relu(W1 f + b1) for all 64 rows
    #pragma unroll
    for (int it = 0; it < 16; ++it) {
        int e = tid + it*256;
        int row = e >> 6, k = e & 63;
        float h = s_f[row*3+0]*s_w1[k*3+0] + s_f[row*3+1]*s_w1[k*3+1]
                + s_f[row*3+2]*s_w1[k*3+2] + s_b1[k];
        s_h1[row*68 + k] = fmaxf(h, 0.f);
    }
    __syncthreads();

    // emb = h1 @ W2^T + b2  (4x4 register tile)
    float4 acc[4];
    #pragma unroll
    for (int i = 0; i < 4; ++i) acc[i] = make_float4(0.f,0.f,0.f,0.f);
    #pragma unroll 8
    for (int kk = 0; kk < 64; ++kk) {
        float4 bb = *(const float4*)&s_w2t[kk*68 + tx*4];
        float a0 = s_h1[(ty*4+0)*68 + kk];
        float a1 = s_h1[(ty*4+1)*68 + kk];
        float a2 = s_h1[(ty*4+2)*68 + kk];
        float a3 = s_h1[(ty*4+3)*68 + kk];
        FMA4(acc[0], a0, bb); FMA4(acc[1], a1, bb);
        FMA4(acc[2], a2, bb); FMA4(acc[3], a3, bb);
    }
    float4 bias = *(const float4*)&s_b2[tx*4];
    #pragma unroll
    for (int i = 0; i < 4; ++i) {
        acc[i].x += bias.x; acc[i].y += bias.y;
        acc[i].z += bias.z; acc[i].w += bias.w;
        float sq = acc[i].x*acc[i].x + acc[i].y*acc[i].y
                 + acc[i].z*acc[i].z + acc[i].w*acc[i].w;
        #pragma unroll
        for (int o = 8; o > 0; o >>= 1) sq += __shfl_xor_sync(0xffffffffu, sq, o);
        float inv = 1.f / fmaxf(sqrtf(sq), 1e-12f);
        int r = base + ty*4 + i;
        *(float4*)&g_emb[r*64 + tx*4] = acc[i];
        if (tx == 0) g_inv[r] = inv;
    }
}

// ---------------- K2: G_t = Nrm^T @ H per (t,b)  [exact R2 body] ---------------
__global__ __launch_bounds__(256) void k_gmat(int layer)
{
    const float4* emb4 = (const float4*)g_emb;
    const float4* h4   = (const float4*)((layer == 0) ? g_emb : g_h1);
    __shared__ __align__(16) float s_A [64*68];
    __shared__ __align__(16) float s_Bh[64*68];
    __shared__ int   s_idx[64];
    __shared__ float s_inv[64];
    int t = blockIdx.x, b = blockIdx.y;
    int tid = threadIdx.x;
    int tx = tid & 15, ty = tid >> 4;
    int Kt = g_cnt[b*Tt + t];
    const int* lst = &g_idx[(b*Tt + t)*Nn];
    float4 acc[4];
    #pragma unroll
    for (int i = 0; i < 4; ++i) acc[i] = make_float4(0.f,0.f,0.f,0.f);

    for (int r0 = 0; r0 < Kt; r0 += 64) {
        __syncthreads();
        if (tid < 64) {
            int row = (r0 + tid < Kt) ? lst[r0 + tid] : -1;
            s_idx[tid] = row;
            s_inv[tid] = (row >= 0) ? g_inv[(b<<10) + row] : 0.f;
        }
        __syncthreads();
        #pragma unroll
        for (int it = 0; it < 4; ++it) {
            int e = tid + it*256;
            int rr = e >> 4, kq = e & 15;
            int row = s_idx[rr];
            float4 v = make_float4(0.f,0.f,0.f,0.f);
            float4 w = make_float4(0.f,0.f,0.f,0.f);
            if (row >= 0) {
                int gi = ((b<<10) + row)*16 + kq;
                v = emb4[gi];
                w = (layer == 0) ? v : h4[gi];
            }
            float iv = s_inv[rr];
            *(float4*)&s_Bh[rr*68 + kq*4] = w;
            v.x *= iv; v.y *= iv; v.z *= iv; v.w *= iv;
            *(float4*)&s_A[rr*68 + kq*4] = v;
        }
        __syncthreads();
        #pragma unroll 8
        for (int rr = 0; rr < 64; ++rr) {
            float4 a  = *(const float4*)&s_A [rr*68 + ty*4];
            float4 bb = *(const float4*)&s_Bh[rr*68 + tx*4];
            FMA4(acc[0], a.x, bb); FMA4(acc[1], a.y, bb);
            FMA4(acc[2], a.z, bb); FMA4(acc[3], a.w, bb);
        }
    }
    float* Gp = &g_G[(b*Tt + t)*4096];
    #pragma unroll
    for (int i = 0; i < 4; ++i)
        *(float4*)&Gp[(ty*4 + i)*64 + tx*4] = acc[i];
}

// ---------------- K2b: M[b,tp] = sum_t sigmoid(C) G[b,t]  [exact R2 body] ------
__global__ __launch_bounds__(128) void k_combine(const float* __restrict__ cont)
{
    __shared__ float s_S[Tt*Tt];
    int b = blockIdx.x, tid = threadIdx.x;
    if (tid < Tt*Tt) s_S[tid] = 1.f / (1.f + expf(-cont[tid]));
    __syncthreads();
    int i4 = blockIdx.y * 128 + tid;       // 0..1023 float4 within 64x64
    const float4* G4 = (const float4*)g_G + (size_t)b*10240;
    float4*       M4 = (float4*)g_M       + (size_t)b*10240;
    float4 g[Tt];
    #pragma unroll
    for (int t = 0; t < Tt; ++t) g[t] = G4[t*1024 + i4];
    #pragma unroll
    for (int tp = 0; tp < Tt; ++tp) {
        float4 o = make_float4(0.f,0.f,0.f,0.f);
        #pragma unroll
        for (int t = 0; t < Tt; ++t) {
            float s = s_S[tp*Tt + t];
            FMA4(o, s, g[t]);
        }
        M4[tp*1024 + i4] = o;
    }
}

// ---------------- K3: Agg = Nrm @ M ; Hout = relu((H+Agg)@W^T+b) [R2 body] -----
// grid (10,64), 256 threads, dyn smem 69632
__global__ __launch_bounds__(256) void k_layer(
    int layer, const float* __restrict__ gnn_w, const float* __restrict__ gnn_b)
{
    const float* hin  = (layer == 0) ? g_emb : g_h1;
    float*       hout = (layer == 0) ? g_h1  : g_h2;
    const float4* emb4 = (const float4*)g_emb;
    extern __shared__ __align__(16) float sm[];
    float* s_B  = sm;               // M   [k][d] stride 68
    float* s_W  = sm + 64*68;       // W^T [k][c] stride 68
    float* s_A  = sm + 2*64*68;     // nrm [r][k] stride 68
    float* s_X  = sm + 3*64*68;     // X   [r][k] stride 68
    __shared__ int   s_idx[64];
    __shared__ float s_inv[64];
    __shared__ __align__(16) float s_bias[64];
    __shared__ __align__(16) float s_csum[16][64];

    int t = blockIdx.x, b = blockIdx.y;
    int tid = threadIdx.x;
    int tx = tid & 15, ty = tid >> 4;
    int Kt = g_cnt[b*Tt + t];
    if (Kt == 0) return;

    const float* Mp = &g_M[(b*Tt + t)*4096];
    const float* Wp = gnn_w + layer*4096;
    #pragma unroll
    for (int it = 0; it < 16; ++it) {
        int e = tid + it*256;
        int r = e >> 6, c = e & 63;
        s_B[r*68 + c] = Mp[e];        // natural [k][d]
        s_W[c*68 + r] = Wp[e];        // transpose of gnn_w -> [k][c]
    }
    if (tid < 64) s_bias[tid] = gnn_b[layer*64 + tid];
    const int* lst = &g_idx[(b*Tt + t)*Nn];

    float4 psum = make_float4(0.f,0.f,0.f,0.f);

    for (int r0 = 0; r0 < Kt; r0 += 64) {
        __syncthreads();
        if (tid < 64) {
            int row = (r0 + tid < Kt) ? lst[r0 + tid] : -1;
            s_idx[tid] = row;
            s_inv[tid] = (row >= 0) ? g_inv[(b<<10) + row] : 0.f;
        }
        __syncthreads();
        #pragma unroll
        for (int it = 0; it < 4; ++it) {
            int e = tid + it*256;
            int rr = e >> 4, kq = e & 15;
            int row = s_idx[rr];
            float4 v = make_float4(0.f,0.f,0.f,0.f);
            if (row >= 0) v = emb4[((b<<10) + row)*16 + kq];
            float iv = s_inv[rr];
            v.x *= iv; v.y *= iv; v.z *= iv; v.w *= iv;
            *(float4*)&s_A[rr*68 + kq*4] = v;
        }
        __syncthreads();

        // GEMM1: Agg[r][d] = sum_k nrm[r][k] M[k][d]
        float4 acc[4];
        #pragma unroll
        for (int i = 0; i < 4; ++i) acc[i] = make_float4(0.f,0.f,0.f,0.f);
        #pragma unroll 8
        for (int kk = 0; kk < 64; ++kk) {
            float4 bb = *(const float4*)&s_B[kk*68 + tx*4];
            float a0 = s_A[(ty*4+0)*68 + kk];
            float a1 = s_A[(ty*4+1)*68 + kk];
            float a2 = s_A[(ty*4+2)*68 + kk];
            float a3 = s_A[(ty*4+3)*68 + kk];
            FMA4(acc[0], a0, bb); FMA4(acc[1], a1, bb);
            FMA4(acc[2], a2, bb); FMA4(acc[3], a3, bb);
        }
        // X = H + Agg (store natural layout)
        #pragma unroll
        for (int i = 0; i < 4; ++i) {
            int row = s_idx[ty*4 + i];
            float4 x = acc[i];
            if (row >= 0) {
                float4 hv = *(const float4*)&hin[((b<<10) + row)*64 + tx*4];
                x.x += hv.x; x.y += hv.y; x.z += hv.z; x.w += hv.w;
            } else {
                x = make_float4(0.f,0.f,0.f,0.f);
            }
            *(float4*)&s_X[(ty*4+i)*68 + tx*4] = x;
        }
        __syncthreads();

        // GEMM2: Out[r][c] = sum_k X[r][k] W[c][k]
        float4 acc2[4];
        #pragma unroll
        for (int i = 0; i < 4; ++i) acc2[i] = make_float4(0.f,0.f,0.f,0.f);
        #pragma unroll 8
        for (int kk = 0; kk < 64; ++kk) {
            float4 bb = *(const float4*)&s_W[kk*68 + tx*4];
            float a0 = s_X[(ty*4+0)*68 + kk];
            float a1 = s_X[(ty*4+1)*68 + kk];
            float a2 = s_X[(ty*4+2)*68 + kk];
            float a3 = s_X[(ty*4+3)*68 + kk];
            FMA4(acc2[0], a0, bb); FMA4(acc2[1], a1, bb);
            FMA4(acc2[2], a2, bb); FMA4(acc2[3], a3, bb);
        }
        float4 bias = *(const float4*)&s_bias[tx*4];
        #pragma unroll
        for (int i = 0; i < 4; ++i) {
            int row = s_idx[ty*4 + i];
            if (row >= 0) {
                float4 o = acc2[i];
                o.x = fmaxf(o.x + bias.x, 0.f);
                o.y = fmaxf(o.y + bias.y, 0.f);
                o.z = fmaxf(o.z + bias.z, 0.f);
                o.w = fmaxf(o.w + bias.w, 0.f);
                *(float4*)&hout[((b<<10) + row)*64 + tx*4] = o;
                if (layer == 1) { psum.x += o.x; psum.y += o.y; psum.z += o.z; psum.w += o.w; }
            }
        }
    }

    if (layer == 1) {
        __syncthreads();
        *(float4*)&s_csum[ty][tx*4] = psum;
        __syncthreads();
        if (tid < 64) {
            float s = 0.f;
            #pragma unroll
            for (int q = 0; q < 16; ++q) s += s_csum[q][tid];
            atomicAdd(&g_ctx[b*64 + tid], s);
        }
    }
}

// ---------------- K4: head (+GRU per block, K reduced to 64) -------------------
__global__ __launch_bounds__(256) void k_head(
    const float* __restrict__ prev, const float* __restrict__ wih,
    const float* __restrict__ whh,  const float* __restrict__ bih,
    const float* __restrict__ bhh,
    const float* __restrict__ w1, const float* __restrict__ b1,
    const float* __restrict__ w2, const float* __restrict__ b2,
    float* __restrict__ out)
{
    __shared__ __align__(16) float s_X[64*68];
    __shared__ __align__(16) float s_W[64*68];
    __shared__ __align__(16) float s_g[320];   // ctx|prev|gi|gh|ns
    __shared__ __align__(16) float s_hs[64];
    __shared__ __align__(16) float s_w2[64];
    int tid = threadIdx.x;
    int tx = tid & 15, ty = tid >> 4;
    int u = blockIdx.x;
    int base = u << 6;
    int b = u >> 4;

    if (tid < 64)  s_g[tid] = g_ctx[b*64 + tid] * (1.f/1024.f);
    else if (tid < 96) s_g[tid] = prev[b*32 + (tid - 64)];
    #pragma unroll
    for (int it = 0; it < 16; ++it) {
        int e = tid + it*256;
        int j = e >> 6, k = e & 63;
        s_W[k*68 + j] = w1[j*96 + k];           // W1[:, :64] transposed
    }
    if (tid < 64) s_w2[tid] = w2[tid];
    const float4* h24 = (const float4*)g_h2;
    #pragma unroll
    for (int it = 0; it < 4; ++it) {
        int e = tid + it*256;
        int rr = e >> 4, kq = e & 15;
        *(float4*)&s_X[rr*68 + kq*4] = h24[(base + rr)*16 + kq];
    }
    __syncthreads();

    if (tid < 96) {
        float gi = bih[tid], gh = bhh[tid];
        #pragma unroll 16
        for (int k = 0; k < 64; ++k) gi += s_g[k] * wih[tid*64 + k];
        #pragma unroll 16
        for (int k = 0; k < 32; ++k) gh += s_g[64 + k] * whh[tid*32 + k];
        s_g[96 + tid] = gi; s_g[192 + tid] = gh;
    }
    __syncthreads();
    if (tid < 32) {
        float r  = 1.f / (1.f + expf(-(s_g[96  + tid] + s_g[192 + tid])));
        float z  = 1.f / (1.f + expf(-(s_g[128 + tid] + s_g[224 + tid])));
        float nn = tanhf(s_g[160 + tid] + r * s_g[256 + tid]);
        float ns = (1.f - z)*nn + z*s_g[64 + tid];
        s_g[288 + tid] = ns;
        if ((u & 15) == 0) out[Bb*Nn + b*32 + tid] = ns;
    }
    __syncthreads();
    if (tid < 64) {
        float v = b1[tid];
        #pragma unroll
        for (int k = 0; k < 32; ++k) v += w1[tid*96 + 64 + k] * s_g[288 + k];
        s_hs[tid] = v;
    }
    __syncthreads();

    float4 hs = *(const float4*)&s_hs[tx*4];
    float4 acc[4] = {hs, hs, hs, hs};
    #pragma unroll 8
    for (int kk = 0; kk < 64; ++kk) {
        float4 bb = *(const float4*)&s_W[kk*68 + tx*4];
        float a0 = s_X[(ty*4+0)*68 + kk];
        float a1 = s_X[(ty*4+1)*68 + kk];
        float a2 = s_X[(ty*4+2)*68 + kk];
        float a3 = s_X[(ty*4+3)*68 + kk];
        FMA4(acc[0], a0, bb); FMA4(acc[1], a1, bb);
        FMA4(acc[2], a2, bb); FMA4(acc[3], a3, bb);
    }
    float4 w2v = *(const float4*)&s_w2[tx*4];
    float b2v = b2[0];
    #pragma unroll
    for (int i = 0; i < 4; ++i) {
        float y = fmaxf(acc[i].x, 0.f)*w2v.x + fmaxf(acc[i].y, 0.f)*w2v.y
                + fmaxf(acc[i].z, 0.f)*w2v.z + fmaxf(acc[i].w, 0.f)*w2v.w;
        #pragma unroll
        for (int o = 8; o > 0; o >>= 1) y += __shfl_xor_sync(0xffffffffu, y, o);
        if (tx == 0) out[base + ty*4 + i] = y + b2v;
    }
}

// ---------------- launch --------------------------------------------------------
extern "C" void kernel_launch(void* const* d_in, const int* in_sizes, int n_in,
                              void* d_out, int out_size)
{
    const float* tf    = (const float*)d_in[0];
    const int*   types = (const int*)  d_in[1];
    const float* prev  = (const float*)d_in[2];
    const float* ew1   = (const float*)d_in[3];
    const float* eb1   = (const float*)d_in[4];
    const float* ew2   = (const float*)d_in[5];
    const float* eb2   = (const float*)d_in[6];
    const float* cont  = (const float*)d_in[7];
    const float* gw    = (const float*)d_in[8];
    const float* gb    = (const float*)d_in[9];
    const float* wih   = (const float*)d_in[10];
    const float* whh   = (const float*)d_in[11];
    const float* bih   = (const float*)d_in[12];
    const float* bhh   = (const float*)d_in[13];
    const float* hw1   = (const float*)d_in[14];
    const float* hb1   = (const float*)d_in[15];
    const float* hw2   = (const float*)d_in[16];
    const float* hb2   = (const float*)d_in[17];
    float* out = (float*)d_out;

    cudaFuncSetAttribute(k_layer, cudaFuncAttributeMaxDynamicSharedMemorySize, 69632);

    k_encbkt<<<1088, 256>>>(tf, types, ew1, eb1, ew2, eb2);
    for (int l = 0; l < 2; ++l) {
        k_gmat   <<<dim3(Tt, Bb), 256>>>(l);
        k_combine<<<dim3(Bb, 8), 128>>>(cont);
        k_layer  <<<dim3(Tt, Bb), 256, 69632>>>(l, gw, gb);
    }
    k_head<<<1024, 256>>>(prev, wih, whh, bih, bhh, hw1, hb1, hw2, hb2, out);
}

// round 9
// speedup vs baseline: 1.1460x; 1.0202x over previous
#include <cuda_runtime.h>
#include <math.h>

#define Bb 64
#define Nn 1024
#define Hh 64
#define Tt 10

// ---------------- scratch (device globals) ------------------------------------
__device__ __align__(16) float g_emb[Bb*Nn*Hh];
__device__ __align__(16) float g_h1 [Bb*Nn*Hh];
__device__ __align__(16) float g_h2 [Bb*Nn*Hh];
__device__ __align__(16) float g_G  [Bb*Tt*Hh*Hh];
__device__ __align__(16) float g_M  [Bb*Tt*Hh*Hh];
__device__ __align__(16) float g_inv[Bb*Nn];
__device__ int   g_idx[Bb*Tt*Nn];
__device__ int   g_cnt[Bb*Tt];
__device__ __align__(16) float g_ctx[Bb*Hh];

typedef unsigned long long ull;

#define FMA4(A, s, v) { (A).x += (s)*(v).x; (A).y += (s)*(v).y; (A).z += (s)*(v).z; (A).w += (s)*(v).w; }
#define FMA2(acc, a2, b2)  asm("fma.rn.f32x2 %0, %1, %2, %0;" : "+l"(acc) : "l"(a2), "l"(b2))
#define PACK_DUP(out, x)   asm("mov.b64 %0, {%1, %1};" : "=l"(out) : "r"(__float_as_uint(x)))
#define UNPACK2(lo, hi, p) asm("mov.b64 {%0, %1}, %2;" : "=r"(lo), "=r"(hi) : "l"(p))

__device__ __forceinline__ float4 acc_f4(ull p0, ull p1) {
    unsigned a, b, c, d;
    UNPACK2(a, b, p0); UNPACK2(c, d, p1);
    return make_float4(__uint_as_float(a), __uint_as_float(b),
                       __uint_as_float(c), __uint_as_float(d));
}

// 16 fp32 FMAs as 8 packed FFMA2: 4 row-scalars x one float4 of B
__device__ __forceinline__ void mk16(ull* acc, float a0, float a1, float a2, float a3,
                                     const float* bp) {
    ulonglong2 bv = *(const ulonglong2*)bp;
    ull ap;
    PACK_DUP(ap, a0); FMA2(acc[0], ap, bv.x); FMA2(acc[1], ap, bv.y);
    PACK_DUP(ap, a1); FMA2(acc[2], ap, bv.x); FMA2(acc[3], ap, bv.y);
    PACK_DUP(ap, a2); FMA2(acc[4], ap, bv.x); FMA2(acc[5], ap, bv.y);
    PACK_DUP(ap, a3); FMA2(acc[6], ap, bv.x); FMA2(acc[7], ap, bv.y);
}

// ---------------- K1: encoder (blocks 0..1023) + bucket (1024..1087) -----------
__global__ __launch_bounds__(256) void k_encbkt(
    const float* __restrict__ tf, const int* __restrict__ types,
    const float* __restrict__ w1, const float* __restrict__ b1,
    const float* __restrict__ w2, const float* __restrict__ b2)
{
    __shared__ __align__(16) float s_h1 [64*68];
    __shared__ __align__(16) float s_w2t[64*68];
    __shared__ __align__(16) float s_f[192];
    __shared__ __align__(16) float s_w1[192];
    __shared__ __align__(16) float s_b1[64];
    __shared__ __align__(16) float s_b2[64];
    __shared__ int s_cnt[16];
    int tid = threadIdx.x;

    if (blockIdx.x >= 1024) {               // ---- bucket path ----
        int b = blockIdx.x - 1024;
        if (tid < Tt) s_cnt[tid] = 0;
        if (tid < 64) g_ctx[b*64 + tid] = 0.f;
        __syncthreads();
        #pragma unroll
        for (int it = 0; it < 4; ++it) {
            int n = it*256 + tid;
            int t = types[b*Nn + n];
            int pos = atomicAdd(&s_cnt[t], 1);
            g_idx[(b*Tt + t)*Nn + pos] = n;
        }
        __syncthreads();
        if (tid < Tt) g_cnt[b*Tt + tid] = s_cnt[tid];
        return;
    }

    int tx = tid & 15, ty = tid >> 4;
    int base = blockIdx.x * 64;

    #pragma unroll
    for (int it = 0; it < 16; ++it) {
        int e = tid + it*256;
        int j = e >> 6, k = e & 63;
        s_w2t[k*68 + j] = w2[e];
    }
    if (tid < 192) { s_f[tid] = tf[base*3 + tid]; s_w1[tid] = w1[tid]; }
    if (tid < 64)  { s_b1[tid] = b1[tid]; s_b2[tid] = b2[tid]; }
    __syncthreads();

    #pragma unroll
    for (int it = 0; it < 16; ++it) {
        int e = tid + it*256;
        int row = e >> 6, k = e & 63;
        float h = s_f[row*3+0]*s_w1[k*3+0] + s_f[row*3+1]*s_w1[k*3+1]
                + s_f[row*3+2]*s_w1[k*3+2] + s_b1[k];
        s_h1[row*68 + k] = fmaxf(h, 0.f);
    }
    __syncthreads();

    float4 acc[4];
    #pragma unroll
    for (int i = 0; i < 4; ++i) acc[i] = make_float4(0.f,0.f,0.f,0.f);
    #pragma unroll 8
    for (int kk = 0; kk < 64; ++kk) {
        float4 bb = *(const float4*)&s_w2t[kk*68 + tx*4];
        float a0 = s_h1[(ty*4+0)*68 + kk];
        float a1 = s_h1[(ty*4+1)*68 + kk];
        float a2 = s_h1[(ty*4+2)*68 + kk];
        float a3 = s_h1[(ty*4+3)*68 + kk];
        FMA4(acc[0], a0, bb); FMA4(acc[1], a1, bb);
        FMA4(acc[2], a2, bb); FMA4(acc[3], a3, bb);
    }
    float4 bias = *(const float4*)&s_b2[tx*4];
    #pragma unroll
    for (int i = 0; i < 4; ++i) {
        acc[i].x += bias.x; acc[i].y += bias.y;
        acc[i].z += bias.z; acc[i].w += bias.w;
        float sq = acc[i].x*acc[i].x + acc[i].y*acc[i].y
                 + acc[i].z*acc[i].z + acc[i].w*acc[i].w;
        #pragma unroll
        for (int o = 8; o > 0; o >>= 1) sq += __shfl_xor_sync(0xffffffffu, sq, o);
        float inv = 1.f / fmaxf(sqrtf(sq), 1e-12f);
        int r = base + ty*4 + i;
        *(float4*)&g_emb[r*64 + tx*4] = acc[i];
        if (tx == 0) g_inv[r] = inv;
    }
}

// ---------------- K2: G_t = Nrm^T @ H per (t,b)  [R2 body] ---------------------
__global__ __launch_bounds__(256) void k_gmat(int layer)
{
    const float4* emb4 = (const float4*)g_emb;
    const float4* h4   = (const float4*)((layer == 0) ? g_emb : g_h1);
    __shared__ __align__(16) float s_A [64*68];
    __shared__ __align__(16) float s_Bh[64*68];
    __shared__ int   s_idx[64];
    __shared__ float s_inv[64];
    int t = blockIdx.x, b = blockIdx.y;
    int tid = threadIdx.x;
    int tx = tid & 15, ty = tid >> 4;
    int Kt = g_cnt[b*Tt + t];
    const int* lst = &g_idx[(b*Tt + t)*Nn];
    float4 acc[4];
    #pragma unroll
    for (int i = 0; i < 4; ++i) acc[i] = make_float4(0.f,0.f,0.f,0.f);

    for (int r0 = 0; r0 < Kt; r0 += 64) {
        __syncthreads();
        if (tid < 64) {
            int row = (r0 + tid < Kt) ? lst[r0 + tid] : -1;
            s_idx[tid] = row;
            s_inv[tid] = (row >= 0) ? g_inv[(b<<10) + row] : 0.f;
        }
        __syncthreads();
        #pragma unroll
        for (int it = 0; it < 4; ++it) {
            int e = tid + it*256;
            int rr = e >> 4, kq = e & 15;
            int row = s_idx[rr];
            float4 v = make_float4(0.f,0.f,0.f,0.f);
            float4 w = make_float4(0.f,0.f,0.f,0.f);
            if (row >= 0) {
                int gi = ((b<<10) + row)*16 + kq;
                v = emb4[gi];
                w = (layer == 0) ? v : h4[gi];
            }
            float iv = s_inv[rr];
            *(float4*)&s_Bh[rr*68 + kq*4] = w;
            v.x *= iv; v.y *= iv; v.z *= iv; v.w *= iv;
            *(float4*)&s_A[rr*68 + kq*4] = v;
        }
        __syncthreads();
        #pragma unroll 8
        for (int rr = 0; rr < 64; ++rr) {
            float4 a  = *(const float4*)&s_A [rr*68 + ty*4];
            float4 bb = *(const float4*)&s_Bh[rr*68 + tx*4];
            FMA4(acc[0], a.x, bb); FMA4(acc[1], a.y, bb);
            FMA4(acc[2], a.z, bb); FMA4(acc[3], a.w, bb);
        }
    }
    float* Gp = &g_G[(b*Tt + t)*4096];
    #pragma unroll
    for (int i = 0; i < 4; ++i)
        *(float4*)&Gp[(ty*4 + i)*64 + tx*4] = acc[i];
}

// ---------------- K2b: M[b,tp] = sum_t sigmoid(C) G[b,t]  [R2 body] ------------
__global__ __launch_bounds__(128) void k_combine(const float* __restrict__ cont)
{
    __shared__ float s_S[Tt*Tt];
    int b = blockIdx.x, tid = threadIdx.x;
    if (tid < Tt*Tt) s_S[tid] = 1.f / (1.f + expf(-cont[tid]));
    __syncthreads();
    int i4 = blockIdx.y * 128 + tid;
    const float4* G4 = (const float4*)g_G + (size_t)b*10240;
    float4*       M4 = (float4*)g_M       + (size_t)b*10240;
    float4 g[Tt];
    #pragma unroll
    for (int t = 0; t < Tt; ++t) g[t] = G4[t*1024 + i4];
    #pragma unroll
    for (int tp = 0; tp < Tt; ++tp) {
        float4 o = make_float4(0.f,0.f,0.f,0.f);
        #pragma unroll
        for (int t = 0; t < Tt; ++t) {
            float s = s_S[tp*Tt + t];
            FMA4(o, s, g[t]);
        }
        M4[tp*1024 + i4] = o;
    }
}

// ---------------- K3: Agg = Nrm @ M ; Hout = relu((H+Agg)@W^T+b) ---------------
// f32x2 + direct __ldg (best measured body) + aliased nrm/X buffer:
// dyn smem = SA(M) 4352 + SW 4352 + SB(nrm/X) 4352 floats = 52224 B -> 4 blk/SM
__global__ __launch_bounds__(256, 4) void k_layer(
    int layer, const float* __restrict__ gnn_w, const float* __restrict__ gnn_b)
{
    const float* hin  = (layer == 0) ? g_emb : g_h1;
    float*       hout = (layer == 0) ? g_h1  : g_h2;
    const float4* emb4 = (const float4*)g_emb;
    extern __shared__ __align__(16) float sm[];
    float* SA = sm;            // M   [k][d] stride 68
    float* SW = sm + 4352;     // W^T [k][c] stride 68
    float* SB = sm + 8704;     // nrm rows, then X rows (aliased), stride 68
    __shared__ __align__(16) float s_bias[64];

    int t = blockIdx.x, b = blockIdx.y;
    int tid = threadIdx.x;
    int tx = tid & 15, ty = tid >> 4;
    int Kt = g_cnt[b*Tt + t];
    if (Kt == 0) return;

    const float* Wp = gnn_w + layer*4096;
    if (tid < 64) s_bias[tid] = gnn_b[layer*64 + tid];
    #pragma unroll
    for (int it = 0; it < 16; ++it) {
        int e = tid + it*256;
        int r = e >> 6, c = e & 63;
        SW[c*68 + r] = Wp[e];                   // transpose -> [k][c]
    }
    const float4* Mp4 = (const float4*)&g_M[(b*Tt + t)*4096];
    #pragma unroll
    for (int it = 0; it < 4; ++it) {
        int e = tid + it*256;
        *(float4*)&SA[(e >> 4)*68 + (e & 15)*4] = Mp4[e];   // natural [k][d]
    }

    const int* lst = &g_idx[(b*Tt + t)*Nn];
    float4 psum = make_float4(0.f,0.f,0.f,0.f);
    __syncthreads();

    for (int r0 = 0; r0 < Kt; r0 += 64) {
        // gather scaled nrm rows into SB
        #pragma unroll
        for (int it = 0; it < 4; ++it) {
            int e = tid + it*256;
            int rr = e >> 4, kq = e & 15;
            int r = r0 + rr;
            float4 v = make_float4(0.f,0.f,0.f,0.f);
            if (r < Kt) {
                int row = __ldg(&lst[r]);
                float iv = __ldg(&g_inv[(b<<10) + row]);
                v = emb4[((b<<10) + row)*16 + kq];
                v.x *= iv; v.y *= iv; v.z *= iv; v.w *= iv;
            }
            *(float4*)&SB[rr*68 + kq*4] = v;
        }
        __syncthreads();

        // GEMM1: Agg = nrm @ M
        ull acc[8] = {0,0,0,0,0,0,0,0};
        #pragma unroll 8
        for (int kk = 0; kk < 64; ++kk) {
            float a0 = SB[(ty*4+0)*68 + kk];
            float a1 = SB[(ty*4+1)*68 + kk];
            float a2 = SB[(ty*4+2)*68 + kk];
            float a3 = SB[(ty*4+3)*68 + kk];
            mk16(acc, a0, a1, a2, a3, &SA[kk*68 + tx*4]);
        }

        // X = H + Agg, held in regs across the buffer swap
        float4 x[4];
        #pragma unroll
        for (int i = 0; i < 4; ++i) {
            int r = r0 + ty*4 + i;
            x[i] = acc_f4(acc[2*i], acc[2*i+1]);
            if (r < Kt) {
                int row = __ldg(&lst[r]);
                float4 hv = *(const float4*)&hin[((b<<10) + row)*64 + tx*4];
                x[i].x += hv.x; x[i].y += hv.y; x[i].z += hv.z; x[i].w += hv.w;
            } else {
                x[i] = make_float4(0.f,0.f,0.f,0.f);
            }
        }
        __syncthreads();       // GEMM1 reads of SB complete
        #pragma unroll
        for (int i = 0; i < 4; ++i)
            *(float4*)&SB[(ty*4+i)*68 + tx*4] = x[i];
        __syncthreads();

        // GEMM2: Out = X @ W^T
        ull acc2[8] = {0,0,0,0,0,0,0,0};
        #pragma unroll 8
        for (int kk = 0; kk < 64; ++kk) {
            float a0 = SB[(ty*4+0)*68 + kk];
            float a1 = SB[(ty*4+1)*68 + kk];
            float a2 = SB[(ty*4+2)*68 + kk];
            float a3 = SB[(ty*4+3)*68 + kk];
            mk16(acc2, a0, a1, a2, a3, &SW[kk*68 + tx*4]);
        }
        float4 bias = *(const float4*)&s_bias[tx*4];
        #pragma unroll
        for (int i = 0; i < 4; ++i) {
            int r = r0 + ty*4 + i;
            if (r < Kt) {
                int row = __ldg(&lst[r]);
                float4 o = acc_f4(acc2[2*i], acc2[2*i+1]);
                o.x = fmaxf(o.x + bias.x, 0.f);
                o.y = fmaxf(o.y + bias.y, 0.f);
                o.z = fmaxf(o.z + bias.z, 0.f);
                o.w = fmaxf(o.w + bias.w, 0.f);
                *(float4*)&hout[((b<<10) + row)*64 + tx*4] = o;
                if (layer == 1) { psum.x += o.x; psum.y += o.y; psum.z += o.z; psum.w += o.w; }
            }
        }
        __syncthreads();       // before next gather overwrites SB
    }

    if (layer == 1) {          // ctx partial sums via SB scratch (loop is done)
        *(float4*)&SB[ty*64 + tx*4] = psum;
        __syncthreads();
        if (tid < 64) {
            float s = 0.f;
            #pragma unroll
            for (int q = 0; q < 16; ++q) s += SB[q*64 + tid];
            atomicAdd(&g_ctx[b*64 + tid], s);
        }
    }
}

// ---------------- K4: head (+GRU per block, K reduced to 64)  [R8 body] --------
__global__ __launch_bounds__(256) void k_head(
    const float* __restrict__ prev, const float* __restrict__ wih,
    const float* __restrict__ whh,  const float* __restrict__ bih,
    const float* __restrict__ bhh,
    const float* __restrict__ w1, const float* __restrict__ b1,
    const float* __restrict__ w2, const float* __restrict__ b2,
    float* __restrict__ out)
{
    __shared__ __align__(16) float s_X[64*68];
    __shared__ __align__(16) float s_W[64*68];
    __shared__ __align__(16) float s_g[320];   // ctx|prev|gi|gh|ns
    __shared__ __align__(16) float s_hs[64];
    __shared__ __align__(16) float s_w2[64];
    int tid = threadIdx.x;
    int tx = tid & 15, ty = tid >> 4;
    int u = blockIdx.x;
    int base = u << 6;
    int b = u >> 4;

    if (tid < 64)  s_g[tid] = g_ctx[b*64 + tid] * (1.f/1024.f);
    else if (tid < 96) s_g[tid] = prev[b*32 + (tid - 64)];
    #pragma unroll
    for (int it = 0; it < 16; ++it) {
        int e = tid + it*256;
        int j = e >> 6, k = e & 63;
        s_W[k*68 + j] = w1[j*96 + k];           // W1[:, :64] transposed
    }
    if (tid < 64) s_w2[tid] = w2[tid];
    const float4* h24 = (const float4*)g_h2;
    #pragma unroll
    for (int it = 0; it < 4; ++it) {
        int e = tid + it*256;
        int rr = e >> 4, kq = e & 15;
        *(float4*)&s_X[rr*68 + kq*4] = h24[(base + rr)*16 + kq];
    }
    __syncthreads();

    if (tid < 96) {
        float gi = bih[tid], gh = bhh[tid];
        #pragma unroll 16
        for (int k = 0; k < 64; ++k) gi += s_g[k] * wih[tid*64 + k];
        #pragma unroll 16
        for (int k = 0; k < 32; ++k) gh += s_g[64 + k] * whh[tid*32 + k];
        s_g[96 + tid] = gi; s_g[192 + tid] = gh;
    }
    __syncthreads();
    if (tid < 32) {
        float r  = 1.f / (1.f + expf(-(s_g[96  + tid] + s_g[192 + tid])));
        float z  = 1.f / (1.f + expf(-(s_g[128 + tid] + s_g[224 + tid])));
        float nn = tanhf(s_g[160 + tid] + r * s_g[256 + tid]);
        float ns = (1.f - z)*nn + z*s_g[64 + tid];
        s_g[288 + tid] = ns;
        if ((u & 15) == 0) out[Bb*Nn + b*32 + tid] = ns;
    }
    __syncthreads();
    if (tid < 64) {
        float v = b1[tid];
        #pragma unroll
        for (int k = 0; k < 32; ++k) v += w1[tid*96 + 64 + k] * s_g[288 + k];
        s_hs[tid] = v;
    }
    __syncthreads();

    float4 hs = *(const float4*)&s_hs[tx*4];
    float4 acc[4] = {hs, hs, hs, hs};
    #pragma unroll 8
    for (int kk = 0; kk < 64; ++kk) {
        float4 bb = *(const float4*)&s_W[kk*68 + tx*4];
        float a0 = s_X[(ty*4+0)*68 + kk];
        float a1 = s_X[(ty*4+1)*68 + kk];
        float a2 = s_X[(ty*4+2)*68 + kk];
        float a3 = s_X[(ty*4+3)*68 + kk];
        FMA4(acc[0], a0, bb); FMA4(acc[1], a1, bb);
        FMA4(acc[2], a2, bb); FMA4(acc[3], a3, bb);
    }
    float4 w2v = *(const float4*)&s_w2[tx*4];
    float b2v = b2[0];
    #pragma unroll
    for (int i = 0; i < 4; ++i) {
        float y = fmaxf(acc[i].x, 0.f)*w2v.x + fmaxf(acc[i].y, 0.f)*w2v.y
                + fmaxf(acc[i].z, 0.f)*w2v.z + fmaxf(acc[i].w, 0.f)*w2v.w;
        #pragma unroll
        for (int o = 8; o > 0; o >>= 1) y += __shfl_xor_sync(0xffffffffu, y, o);
        if (tx == 0) out[base + ty*4 + i] = y + b2v;
    }
}

// ---------------- launch --------------------------------------------------------
extern "C" void kernel_launch(void* const* d_in, const int* in_sizes, int n_in,
                              void* d_out, int out_size)
{
    const float* tf    = (const float*)d_in[0];
    const int*   types = (const int*)  d_in[1];
    const float* prev  = (const float*)d_in[2];
    const float* ew1   = (const float*)d_in[3];
    const float* eb1   = (const float*)d_in[4];
    const float* ew2   = (const float*)d_in[5];
    const float* eb2   = (const float*)d_in[6];
    const float* cont  = (const float*)d_in[7];
    const float* gw    = (const float*)d_in[8];
    const float* gb    = (const float*)d_in[9];
    const float* wih   = (const float*)d_in[10];
    const float* whh   = (const float*)d_in[11];
    const float* bih   = (const float*)d_in[12];
    const float* bhh   = (const float*)d_in[13];
    const float* hw1   = (const float*)d_in[14];
    const float* hb1   = (const float*)d_in[15];
    const float* hw2   = (const float*)d_in[16];
    const float* hb2   = (const float*)d_in[17];
    float* out = (float*)d_out;

    cudaFuncSetAttribute(k_layer, cudaFuncAttributeMaxDynamicSharedMemorySize, 52224);

    k_encbkt<<<1088, 256>>>(tf, types, ew1, eb1, ew2, eb2);
    for (int l = 0; l < 2; ++l) {
        k_gmat   <<<dim3(Tt, Bb), 256>>>(l);
        k_combine<<<dim3(Bb, 8), 128>>>(cont);
        k_layer  <<<dim3(Tt, Bb), 256, 52224>>>(l, gw, gb);
    }
    k_head<<<1024, 256>>>(prev, wih, whh, bih, bhh, hw1, hb1, hw2, hb2, out);
}

// round 10
// speedup vs baseline: 1.1740x; 1.0244x over previous
#include <cuda_runtime.h>
#include <math.h>

#define Bb 64
#define Nn 1024
#define Hh 64
#define Tt 10

// ---------------- scratch (device globals; permuted row space) -----------------
__device__ __align__(16) float g_embP[Bb*Nn*Hh];   // emb rows in bucket order
__device__ __align__(16) float g_nrmP[Bb*Nn*Hh];   // emb/||emb|| rows, bucket order
__device__ __align__(16) float g_h1P [Bb*Nn*Hh];
__device__ __align__(16) float g_h2P [Bb*Nn*Hh];
__device__ __align__(16) float g_G  [Bb*Tt*Hh*Hh];
__device__ __align__(16) float g_M  [Bb*Tt*Hh*Hh];
__device__ int g_pos[Bb*Nn];                       // orig row -> absolute permuted row
__device__ int g_off[Bb*Tt];
__device__ int g_cnt[Bb*Tt];
__device__ __align__(16) float g_ctx[Bb*Hh];

typedef unsigned long long ull;

#define FMA4(A, s, v) { (A).x += (s)*(v).x; (A).y += (s)*(v).y; (A).z += (s)*(v).z; (A).w += (s)*(v).w; }
#define FMA2(acc, a2, b2)  asm("fma.rn.f32x2 %0, %1, %2, %0;" : "+l"(acc) : "l"(a2), "l"(b2))
#define PACK_DUP(out, x)   asm("mov.b64 %0, {%1, %1};" : "=l"(out) : "r"(__float_as_uint(x)))
#define UNPACK2(lo, hi, p) asm("mov.b64 {%0, %1}, %2;" : "=r"(lo), "=r"(hi) : "l"(p))

// PDL primitives (sm_90+)
#define GDC_WAIT()   asm volatile("griddepcontrol.wait;" ::: "memory")
#define GDC_LAUNCH() asm volatile("griddepcontrol.launch_dependents;" ::: "memory")

__device__ __forceinline__ float4 acc_f4(ull p0, ull p1) {
    unsigned a, b, c, d;
    UNPACK2(a, b, p0); UNPACK2(c, d, p1);
    return make_float4(__uint_as_float(a), __uint_as_float(b),
                       __uint_as_float(c), __uint_as_float(d));
}

// 16 fp32 FMAs as 8 packed FFMA2
__device__ __forceinline__ void mk16(ull* acc, float a0, float a1, float a2, float a3,
                                     const float* bp) {
    ulonglong2 bv = *(const ulonglong2*)bp;
    ull ap;
    PACK_DUP(ap, a0); FMA2(acc[0], ap, bv.x); FMA2(acc[1], ap, bv.y);
    PACK_DUP(ap, a1); FMA2(acc[2], ap, bv.x); FMA2(acc[3], ap, bv.y);
    PACK_DUP(ap, a2); FMA2(acc[4], ap, bv.x); FMA2(acc[5], ap, bv.y);
    PACK_DUP(ap, a3); FMA2(acc[6], ap, bv.x); FMA2(acc[7], ap, bv.y);
}

// ---------------- K0: bucket (needs only types) --------------------------------
__global__ __launch_bounds__(1024) void k_bucket(const int* __restrict__ types)
{
    __shared__ int s_cnt[16];
    __shared__ int s_off[16];
    int b = blockIdx.x, n = threadIdx.x;
    if (n < Tt) s_cnt[n] = 0;
    if (n < 64) g_ctx[b*64 + n] = 0.f;
    __syncthreads();
    int t = types[b*Nn + n];
    int rank = atomicAdd(&s_cnt[t], 1);
    __syncthreads();
    if (n == 0) {
        int a = 0;
        #pragma unroll
        for (int i = 0; i < Tt; ++i) { s_off[i] = a; a += s_cnt[i]; }
    }
    __syncthreads();
    g_pos[b*Nn + n] = b*Nn + s_off[t] + rank;
    if (n < Tt) { g_cnt[b*Tt + n] = s_cnt[n]; g_off[b*Tt + n] = s_off[n]; }
    GDC_LAUNCH();
}

// ---------------- K1: encoder -> permuted emb/nrm ------------------------------
__global__ __launch_bounds__(256) void k_enc(
    const float* __restrict__ tf,
    const float* __restrict__ w1, const float* __restrict__ b1,
    const float* __restrict__ w2, const float* __restrict__ b2)
{
    __shared__ __align__(16) float s_h1 [64*68];
    __shared__ __align__(16) float s_w2t[64*68];
    __shared__ __align__(16) float s_f[192];
    __shared__ __align__(16) float s_w1[192];
    __shared__ __align__(16) float s_b1[64];
    __shared__ __align__(16) float s_b2[64];
    int tid = threadIdx.x;
    int tx = tid & 15, ty = tid >> 4;
    int base = blockIdx.x * 64;

    #pragma unroll
    for (int it = 0; it < 16; ++it) {
        int e = tid + it*256;
        int j = e >> 6, k = e & 63;
        s_w2t[k*68 + j] = w2[e];
    }
    if (tid < 192) { s_f[tid] = tf[base*3 + tid]; s_w1[tid] = w1[tid]; }
    if (tid < 64)  { s_b1[tid] = b1[tid]; s_b2[tid] = b2[tid]; }
    __syncthreads();
    GDC_LAUNCH();

    #pragma unroll
    for (int it = 0; it < 16; ++it) {
        int e = tid + it*256;
        int row = e >> 6, k = e & 63;
        float h = s_f[row*3+0]*s_w1[k*3+0] + s_f[row*3+1]*s_w1[k*3+1]
                + s_f[row*3+2]*s_w1[k*3+2] + s_b1[k];
        s_h1[row*68 + k] = fmaxf(h, 0.f);
    }
    __syncthreads();

    float4 acc[4];
    #pragma unroll
    for (int i = 0; i < 4; ++i) acc[i] = make_float4(0.f,0.f,0.f,0.f);
    #pragma unroll 8
    for (int kk = 0; kk < 64; ++kk) {
        float4 bb = *(const float4*)&s_w2t[kk*68 + tx*4];
        float a0 = s_h1[(ty*4+0)*68 + kk];
        float a1 = s_h1[(ty*4+1)*68 + kk];
        float a2 = s_h1[(ty*4+2)*68 + kk];
        float a3 = s_h1[(ty*4+3)*68 + kk];
        FMA4(acc[0], a0, bb); FMA4(acc[1], a1, bb);
        FMA4(acc[2], a2, bb); FMA4(acc[3], a3, bb);
    }
    float4 bias = *(const float4*)&s_b2[tx*4];
    GDC_WAIT();                    // before reading g_pos (bucket output)
    #pragma unroll
    for (int i = 0; i < 4; ++i) {
        acc[i].x += bias.x; acc[i].y += bias.y;
        acc[i].z += bias.z; acc[i].w += bias.w;
        float sq = acc[i].x*acc[i].x + acc[i].y*acc[i].y
                 + acc[i].z*acc[i].z + acc[i].w*acc[i].w;
        #pragma unroll
        for (int o = 8; o > 0; o >>= 1) sq += __shfl_xor_sync(0xffffffffu, sq, o);
        float inv = 1.f / fmaxf(sqrtf(sq), 1e-12f);
        int p = g_pos[base + ty*4 + i];
        *(float4*)&g_embP[p*64 + tx*4] = acc[i];
        float4 nv = make_float4(acc[i].x*inv, acc[i].y*inv, acc[i].z*inv, acc[i].w*inv);
        *(float4*)&g_nrmP[p*64 + tx*4] = nv;
    }
}

// ---------------- K2: G_t = NrmP^T @ HP per (t,b), dense rows ------------------
__global__ __launch_bounds__(256) void k_gmat(int layer)
{
    const float4* nrm4 = (const float4*)g_nrmP;
    const float4* h4   = (const float4*)((layer == 0) ? g_embP : g_h1P);
    __shared__ __align__(16) float s_A [64*68];
    __shared__ __align__(16) float s_Bh[64*68];
    int t = blockIdx.x, b = blockIdx.y;
    int tid = threadIdx.x;
    int tx = tid & 15, ty = tid >> 4;
    GDC_WAIT(); GDC_LAUNCH();
    int Kt = g_cnt[b*Tt + t];
    int rbase = (b << 10) + g_off[b*Tt + t];
    float4 acc[4];
    #pragma unroll
    for (int i = 0; i < 4; ++i) acc[i] = make_float4(0.f,0.f,0.f,0.f);

    for (int r0 = 0; r0 < Kt; r0 += 64) {
        #pragma unroll
        for (int it = 0; it < 4; ++it) {
            int e = tid + it*256;
            int rr = e >> 4, kq = e & 15;
            int r = r0 + rr;
            float4 a = make_float4(0.f,0.f,0.f,0.f);
            float4 w = make_float4(0.f,0.f,0.f,0.f);
            if (r < Kt) {
                int gi = (rbase + r)*16 + kq;
                a = nrm4[gi];
                w = h4[gi];
            }
            *(float4*)&s_A [rr*68 + kq*4] = a;
            *(float4*)&s_Bh[rr*68 + kq*4] = w;
        }
        __syncthreads();
        #pragma unroll 8
        for (int rr = 0; rr < 64; ++rr) {
            float4 a  = *(const float4*)&s_A [rr*68 + ty*4];
            float4 bb = *(const float4*)&s_Bh[rr*68 + tx*4];
            FMA4(acc[0], a.x, bb); FMA4(acc[1], a.y, bb);
            FMA4(acc[2], a.z, bb); FMA4(acc[3], a.w, bb);
        }
        __syncthreads();
    }
    float* Gp = &g_G[(b*Tt + t)*4096];
    #pragma unroll
    for (int i = 0; i < 4; ++i)
        *(float4*)&Gp[(ty*4 + i)*64 + tx*4] = acc[i];
}

// ---------------- K2b: M[b,tp] = sum_t sigmoid(C) G[b,t] -----------------------
__global__ __launch_bounds__(128) void k_combine(const float* __restrict__ cont)
{
    __shared__ float s_S[Tt*Tt];
    int b = blockIdx.x, tid = threadIdx.x;
    if (tid < Tt*Tt) s_S[tid] = 1.f / (1.f + expf(-cont[tid]));
    __syncthreads();
    GDC_WAIT(); GDC_LAUNCH();
    int i4 = blockIdx.y * 128 + tid;
    const float4* G4 = (const float4*)g_G + (size_t)b*10240;
    float4*       M4 = (float4*)g_M       + (size_t)b*10240;
    float4 g[Tt];
    #pragma unroll
    for (int t = 0; t < Tt; ++t) g[t] = G4[t*1024 + i4];
    #pragma unroll
    for (int tp = 0; tp < Tt; ++tp) {
        float4 o = make_float4(0.f,0.f,0.f,0.f);
        #pragma unroll
        for (int t = 0; t < Tt; ++t) {
            float s = s_S[tp*Tt + t];
            FMA4(o, s, g[t]);
        }
        M4[tp*1024 + i4] = o;
    }
}

// ---------------- K3: Agg = NrmP @ M ; HoutP = relu((HP+Agg)@W^T+b) ------------
// dense permuted rows, coalesced stores; smem 52224 -> 4 blk/SM
__global__ __launch_bounds__(256, 4) void k_layer(
    int layer, const float* __restrict__ gnn_w, const float* __restrict__ gnn_b)
{
    const float* hin  = (layer == 0) ? g_embP : g_h1P;
    float*       hout = (layer == 0) ? g_h1P  : g_h2P;
    const float4* nrm4 = (const float4*)g_nrmP;
    extern __shared__ __align__(16) float sm[];
    float* SA = sm;            // M   [k][d] stride 68
    float* SW = sm + 4352;     // W^T [k][c] stride 68
    float* SB = sm + 8704;     // nrm rows, then X rows (aliased), stride 68
    __shared__ __align__(16) float s_bias[64];

    int t = blockIdx.x, b = blockIdx.y;
    int tid = threadIdx.x;
    int tx = tid & 15, ty = tid >> 4;

    const float* Wp = gnn_w + layer*4096;
    if (tid < 64) s_bias[tid] = gnn_b[layer*64 + tid];
    #pragma unroll
    for (int it = 0; it < 16; ++it) {
        int e = tid + it*256;
        SW[(e & 63)*68 + (e >> 6)] = Wp[e];     // transpose -> [k][c]
    }
    GDC_WAIT(); GDC_LAUNCH();
    int Kt = g_cnt[b*Tt + t];
    if (Kt == 0) return;
    int rbase = (b << 10) + g_off[b*Tt + t];

    const float4* Mp4 = (const float4*)&g_M[(b*Tt + t)*4096];
    #pragma unroll
    for (int it = 0; it < 4; ++it) {
        int e = tid + it*256;
        *(float4*)&SA[(e >> 4)*68 + (e & 15)*4] = Mp4[e];
    }
    float4 psum = make_float4(0.f,0.f,0.f,0.f);
    __syncthreads();

    for (int r0 = 0; r0 < Kt; r0 += 64) {
        // dense gather of pre-scaled nrm rows
        #pragma unroll
        for (int it = 0; it < 4; ++it) {
            int e = tid + it*256;
            int rr = e >> 4, kq = e & 15;
            int r = r0 + rr;
            float4 v = make_float4(0.f,0.f,0.f,0.f);
            if (r < Kt) v = nrm4[(rbase + r)*16 + kq];
            *(float4*)&SB[rr*68 + kq*4] = v;
        }
        __syncthreads();

        // GEMM1: Agg = nrm @ M
        ull acc[8] = {0,0,0,0,0,0,0,0};
        #pragma unroll 8
        for (int kk = 0; kk < 64; ++kk) {
            float a0 = SB[(ty*4+0)*68 + kk];
            float a1 = SB[(ty*4+1)*68 + kk];
            float a2 = SB[(ty*4+2)*68 + kk];
            float a3 = SB[(ty*4+3)*68 + kk];
            mk16(acc, a0, a1, a2, a3, &SA[kk*68 + tx*4]);
        }

        // X = H + Agg (regs across buffer swap)
        float4 x[4];
        #pragma unroll
        for (int i = 0; i < 4; ++i) {
            int r = r0 + ty*4 + i;
            x[i] = acc_f4(acc[2*i], acc[2*i+1]);
            if (r < Kt) {
                float4 hv = *(const float4*)&hin[(rbase + r)*64 + tx*4];
                x[i].x += hv.x; x[i].y += hv.y; x[i].z += hv.z; x[i].w += hv.w;
            } else {
                x[i] = make_float4(0.f,0.f,0.f,0.f);
            }
        }
        __syncthreads();
        #pragma unroll
        for (int i = 0; i < 4; ++i)
            *(float4*)&SB[(ty*4+i)*68 + tx*4] = x[i];
        __syncthreads();

        // GEMM2: Out = X @ W^T
        ull acc2[8] = {0,0,0,0,0,0,0,0};
        #pragma unroll 8
        for (int kk = 0; kk < 64; ++kk) {
            float a0 = SB[(ty*4+0)*68 + kk];
            float a1 = SB[(ty*4+1)*68 + kk];
            float a2 = SB[(ty*4+2)*68 + kk];
            float a3 = SB[(ty*4+3)*68 + kk];
            mk16(acc2, a0, a1, a2, a3, &SW[kk*68 + tx*4]);
        }
        float4 bias = *(const float4*)&s_bias[tx*4];
        #pragma unroll
        for (int i = 0; i < 4; ++i) {
            int r = r0 + ty*4 + i;
            if (r < Kt) {
                float4 o = acc_f4(acc2[2*i], acc2[2*i+1]);
                o.x = fmaxf(o.x + bias.x, 0.f);
                o.y = fmaxf(o.y + bias.y, 0.f);
                o.z = fmaxf(o.z + bias.z, 0.f);
                o.w = fmaxf(o.w + bias.w, 0.f);
                *(float4*)&hout[(rbase + r)*64 + tx*4] = o;   // coalesced
                if (layer == 1) { psum.x += o.x; psum.y += o.y; psum.z += o.z; psum.w += o.w; }
            }
        }
        __syncthreads();
    }

    if (layer == 1) {
        *(float4*)&SB[ty*64 + tx*4] = psum;
        __syncthreads();
        if (tid < 64) {
            float s = 0.f;
            #pragma unroll
            for (int q = 0; q < 16; ++q) s += SB[q*64 + tid];
            atomicAdd(&g_ctx[b*64 + tid], s);
        }
    }
}

// ---------------- K4: head (+GRU per block, K=64, gathers h2P via pos) ---------
__global__ __launch_bounds__(256) void k_head(
    const float* __restrict__ prev, const float* __restrict__ wih,
    const float* __restrict__ whh,  const float* __restrict__ bih,
    const float* __restrict__ bhh,
    const float* __restrict__ w1, const float* __restrict__ b1,
    const float* __restrict__ w2, const float* __restrict__ b2,
    float* __restrict__ out)
{
    __shared__ __align__(16) float s_X[64*68];
    __shared__ __align__(16) float s_W[64*68];
    __shared__ __align__(16) float s_g[320];   // ctx|prev|gi|gh|ns
    __shared__ __align__(16) float s_hs[64];
    __shared__ __align__(16) float s_w2[64];
    __shared__ int s_pos[64];
    int tid = threadIdx.x;
    int tx = tid & 15, ty = tid >> 4;
    int u = blockIdx.x;
    int base = u << 6;
    int b = u >> 4;

    // independent staging
    #pragma unroll
    for (int it = 0; it < 16; ++it) {
        int e = tid + it*256;
        int j = e >> 6, k = e & 63;
        s_W[k*68 + j] = w1[j*96 + k];           // W1[:, :64] transposed
    }
    if (tid < 64) s_w2[tid] = w2[tid];
    GDC_WAIT();
    if (tid < 64)       s_g[tid] = g_ctx[b*64 + tid] * (1.f/1024.f);
    else if (tid < 96)  s_g[tid] = prev[b*32 + (tid - 64)];
    else if (tid < 160) s_pos[tid - 96] = g_pos[base + (tid - 96)];
    __syncthreads();

    // gather h2P rows via pos + GRU stage 1
    const float4* h24 = (const float4*)g_h2P;
    #pragma unroll
    for (int it = 0; it < 4; ++it) {
        int e = tid + it*256;
        int rr = e >> 4, kq = e & 15;
        *(float4*)&s_X[rr*68 + kq*4] = h24[s_pos[rr]*16 + kq];
    }
    if (tid < 96) {
        float gi = bih[tid], gh = bhh[tid];
        #pragma unroll 16
        for (int k = 0; k < 64; ++k) gi += s_g[k] * wih[tid*64 + k];
        #pragma unroll 16
        for (int k = 0; k < 32; ++k) gh += s_g[64 + k] * whh[tid*32 + k];
        s_g[96 + tid] = gi; s_g[192 + tid] = gh;
    }
    __syncthreads();
    if (tid < 32) {
        float r  = 1.f / (1.f + expf(-(s_g[96  + tid] + s_g[192 + tid])));
        float z  = 1.f / (1.f + expf(-(s_g[128 + tid] + s_g[224 + tid])));
        float nn = tanhf(s_g[160 + tid] + r * s_g[256 + tid]);
        float ns = (1.f - z)*nn + z*s_g[64 + tid];
        s_g[288 + tid] = ns;
        if ((u & 15) == 0) out[Bb*Nn + b*32 + tid] = ns;
    }
    __syncthreads();
    if (tid < 64) {
        float v = b1[tid];
        #pragma unroll
        for (int k = 0; k < 32; ++k) v += w1[tid*96 + 64 + k] * s_g[288 + k];
        s_hs[tid] = v;
    }
    __syncthreads();

    float4 hs = *(const float4*)&s_hs[tx*4];
    float4 acc[4] = {hs, hs, hs, hs};
    #pragma unroll 8
    for (int kk = 0; kk < 64; ++kk) {
        float4 bb = *(const float4*)&s_W[kk*68 + tx*4];
        float a0 = s_X[(ty*4+0)*68 + kk];
        float a1 = s_X[(ty*4+1)*68 + kk];
        float a2 = s_X[(ty*4+2)*68 + kk];
        float a3 = s_X[(ty*4+3)*68 + kk];
        FMA4(acc[0], a0, bb); FMA4(acc[1], a1, bb);
        FMA4(acc[2], a2, bb); FMA4(acc[3], a3, bb);
    }
    float4 w2v = *(const float4*)&s_w2[tx*4];
    float b2v = b2[0];
    #pragma unroll
    for (int i = 0; i < 4; ++i) {
        float y = fmaxf(acc[i].x, 0.f)*w2v.x + fmaxf(acc[i].y, 0.f)*w2v.y
                + fmaxf(acc[i].z, 0.f)*w2v.z + fmaxf(acc[i].w, 0.f)*w2v.w;
        #pragma unroll
        for (int o = 8; o > 0; o >>= 1) y += __shfl_xor_sync(0xffffffffu, y, o);
        if (tx == 0) out[base + ty*4 + i] = y + b2v;
    }
}

// ---------------- launch --------------------------------------------------------
extern "C" void kernel_launch(void* const* d_in, const int* in_sizes, int n_in,
                              void* d_out, int out_size)
{
    const float* tf    = (const float*)d_in[0];
    const int*   types = (const int*)  d_in[1];
    const float* prev  = (const float*)d_in[2];
    const float* ew1   = (const float*)d_in[3];
    const float* eb1   = (const float*)d_in[4];
    const float* ew2   = (const float*)d_in[5];
    const float* eb2   = (const float*)d_in[6];
    const float* cont  = (const float*)d_in[7];
    const float* gw    = (const float*)d_in[8];
    const float* gb    = (const float*)d_in[9];
    const float* wih   = (const float*)d_in[10];
    const float* whh   = (const float*)d_in[11];
    const float* bih   = (const float*)d_in[12];
    const float* bhh   = (const float*)d_in[13];
    const float* hw1   = (const float*)d_in[14];
    const float* hb1   = (const float*)d_in[15];
    const float* hw2   = (const float*)d_in[16];
    const float* hb2   = (const float*)d_in[17];
    float* out = (float*)d_out;

    cudaFuncSetAttribute(k_layer, cudaFuncAttributeMaxDynamicSharedMemorySize, 52224);

    cudaLaunchAttribute at;
    at.id = cudaLaunchAttributeProgrammaticStreamSerialization;
    at.val.programmaticStreamSerializationAllowed = 1;
    cudaLaunchConfig_t cfg = {};
    cfg.attrs = &at;
    cfg.numAttrs = 1;
    cfg.stream = 0;

    k_bucket<<<Bb, 1024>>>(types);

    cfg.gridDim = dim3(1024); cfg.blockDim = dim3(256); cfg.dynamicSmemBytes = 0;
    cudaLaunchKernelEx(&cfg, k_enc, tf, ew1, eb1, ew2, eb2);

    for (int l = 0; l < 2; ++l) {
        cfg.gridDim = dim3(Tt, Bb); cfg.blockDim = dim3(256); cfg.dynamicSmemBytes = 0;
        cudaLaunchKernelEx(&cfg, k_gmat, l);
        cfg.gridDim = dim3(Bb, 8); cfg.blockDim = dim3(128); cfg.dynamicSmemBytes = 0;
        cudaLaunchKernelEx(&cfg, k_combine, cont);
        cfg.gridDim = dim3(Tt, Bb); cfg.blockDim = dim3(256); cfg.dynamicSmemBytes = 52224;
        cudaLaunchKernelEx(&cfg, k_layer, l, gw, gb);
    }
    cfg.gridDim = dim3(1024); cfg.blockDim = dim3(256); cfg.dynamicSmemBytes = 0;
    cudaLaunchKernelEx(&cfg, k_head, prev, wih, whh, bih, bhh,
                       hw1, hb1, hw2, hb2, out);
}